// round 14
// baseline (speedup 1.0000x reference)
#include <cuda_runtime.h>
#include <cuda_bf16.h>
#include <cuda_fp16.h>
#include <math.h>
#include <stdint.h>

// Problem constants
#define BATCH 16
#define NPATCH 4096
#define KTOK 32
#define DIM 512
#define DHEAD 256
#define SCALE_V 0.0625f   // 256^-0.5

#define SPLITS 16         // fused grid = 16 x 16 = 256 blocks, occ 2
#define NBLK_MT 256       // mega_tail blocks (must all be co-resident)

// Scratch (no allocation allowed -> device globals)
__device__ __half g_Qkh [BATCH*KTOK*DIM];
__device__ float  g_Gp  [SPLITS*BATCH*KTOK*DIM];
__device__ float  g_G   [BATCH*KTOK*DIM];
__device__ float  g_F   [BATCH*KTOK*DHEAD];
__device__ float  g_rows[BATCH*KTOK*SPLITS];
__device__ uint4  g_Wvf [32*32*32];   // Wv fragments (hi/lo)
__device__ uint4  g_Wof [64*16*32];   // Wo fragments (hi/lo)
__device__ uint2  g_Wqf [32*32*32];   // Wq fragments (fp16)
__device__ uint2  g_Wkf [64*16*32];   // Wk^T fragments (fp16)
__device__ unsigned g_barcnt;
__device__ unsigned g_bargen;

// ---------------------------------------------------------------------------

#define LDSM4(R0,R1,R2,R3,ADDR) \
    asm volatile("ldmatrix.sync.aligned.m8n8.x4.shared.b16 {%0,%1,%2,%3}, [%4];" \
        : "=r"(R0),"=r"(R1),"=r"(R2),"=r"(R3) : "r"(ADDR))

#define LDSM4T(R0,R1,R2,R3,ADDR) \
    asm volatile("ldmatrix.sync.aligned.m8n8.x4.trans.shared.b16 {%0,%1,%2,%3}, [%4];" \
        : "=r"(R0),"=r"(R1),"=r"(R2),"=r"(R3) : "r"(ADDR))

#define MMA_F16(C,A,B0,B1) \
    asm volatile("mma.sync.aligned.m16n8k16.row.col.f32.f16.f16.f32 " \
        "{%0,%1,%2,%3},{%4,%5,%6,%7},{%8,%9},{%0,%1,%2,%3};" \
        : "+f"((C)[0]),"+f"((C)[1]),"+f"((C)[2]),"+f"((C)[3]) \
        : "r"((A)[0]),"r"((A)[1]),"r"((A)[2]),"r"((A)[3]),"r"(B0),"r"(B1))

__device__ __forceinline__ uint32_t cvta_s(const void* p) {
    return (uint32_t)__cvta_generic_to_shared(p);
}

__device__ __forceinline__ uint2 cvt_h4(float4 v) {
    __half2 h0 = __floats2half2_rn(v.x, v.y);
    __half2 h1 = __floats2half2_rn(v.z, v.w);
    uint2 r; r.x = *(uint32_t*)&h0; r.y = *(uint32_t*)&h1; return r;
}

__device__ __forceinline__ void cvt_split4h(float4 v, uint2 &hi, uint2 &lo) {
    __half2 h0 = __floats2half2_rn(v.x, v.y);
    __half2 h1 = __floats2half2_rn(v.z, v.w);
    float rx = v.x - __half2float(h0.x);
    float ry = v.y - __half2float(h0.y);
    float rz = v.z - __half2float(h1.x);
    float rw = v.w - __half2float(h1.y);
    __half2 l0 = __floats2half2_rn(rx, ry);
    __half2 l1 = __floats2half2_rn(rz, rw);
    hi.x = *(uint32_t*)&h0; hi.y = *(uint32_t*)&h1;
    lo.x = *(uint32_t*)&l0; lo.y = *(uint32_t*)&l1;
}

// Grid-wide barrier for mega_tail (all NBLK_MT blocks co-resident: occ 2).
__device__ __forceinline__ void grid_barrier() {
    __syncthreads();
    if (threadIdx.x == 0) {
        __threadfence();
        unsigned gen = atomicAdd(&g_bargen, 0u);
        if (atomicAdd(&g_barcnt, 1u) == NBLK_MT - 1u) {
            atomicExch(&g_barcnt, 0u);
            __threadfence();
            atomicAdd(&g_bargen, 1u);
        } else {
            while (atomicAdd(&g_bargen, 0u) == gen) { __nanosleep(64); }
        }
    }
    __syncthreads();
}

// ===========================================================================
// prep_wfrag2: build all weight fragment arrays. 512 blocks x 256 thr.
//   grp 0: Wvf (hi/lo, B[n][k]=Wv[n][k],  KIN=512, K16=32, n8<32)
//   grp 1: Wof (hi/lo, B[n][k]=Wo[n][k],  KIN=256, K16=16, n8<64)
//   grp 2: Wqf (fp16,  B[n][k]=Wq[n][k],  KIN=512, K16=32, n8<32)
//   grp 3: Wkf (fp16,  B[n][k]=Wk[k][n],  K=256 rows of Wk, K16=16, n8<64)
// ===========================================================================
__global__ __launch_bounds__(256)
void prep_wfrag2(const float* __restrict__ Wq, const float* __restrict__ Wk,
                 const float* __restrict__ Wv, const float* __restrict__ Wo,
                 uint2* __restrict__ Wqf, uint2* __restrict__ Wkf,
                 uint4* __restrict__ Wvf, uint4* __restrict__ Wof)
{
    int t = blockIdx.x*256 + threadIdx.x;
    int lane = t & 31;
    int f    = (t >> 5) & 1023;
    int grp  = t >> 15;

    if (grp == 0) {          // Wvf hi/lo
        int k16 = f & 31, n8 = f >> 5;
        int n = n8*8 + (lane >> 2);
        int k = k16*16 + (lane & 3)*2;
        float w00 = Wv[(long)n*512 + k],     w01 = Wv[(long)n*512 + k + 1];
        float w10 = Wv[(long)n*512 + k + 8], w11 = Wv[(long)n*512 + k + 9];
        __half2 h0 = __floats2half2_rn(w00, w01);
        __half2 h1 = __floats2half2_rn(w10, w11);
        __half2 l0 = __floats2half2_rn(w00 - __half2float(h0.x), w01 - __half2float(h0.y));
        __half2 l1 = __floats2half2_rn(w10 - __half2float(h1.x), w11 - __half2float(h1.y));
        uint4 r;
        r.x = *(uint32_t*)&h0; r.y = *(uint32_t*)&h1;
        r.z = *(uint32_t*)&l0; r.w = *(uint32_t*)&l1;
        Wvf[(long)f*32 + lane] = r;
    } else if (grp == 1) {   // Wof hi/lo
        int k16 = f & 15, n8 = f >> 4;
        int n = n8*8 + (lane >> 2);
        int k = k16*16 + (lane & 3)*2;
        float w00 = Wo[(long)n*256 + k],     w01 = Wo[(long)n*256 + k + 1];
        float w10 = Wo[(long)n*256 + k + 8], w11 = Wo[(long)n*256 + k + 9];
        __half2 h0 = __floats2half2_rn(w00, w01);
        __half2 h1 = __floats2half2_rn(w10, w11);
        __half2 l0 = __floats2half2_rn(w00 - __half2float(h0.x), w01 - __half2float(h0.y));
        __half2 l1 = __floats2half2_rn(w10 - __half2float(h1.x), w11 - __half2float(h1.y));
        uint4 r;
        r.x = *(uint32_t*)&h0; r.y = *(uint32_t*)&h1;
        r.z = *(uint32_t*)&l0; r.w = *(uint32_t*)&l1;
        Wof[(long)f*32 + lane] = r;
    } else if (grp == 2) {   // Wqf fp16
        int k16 = f & 31, n8 = f >> 5;
        int n = n8*8 + (lane >> 2);
        int k = k16*16 + (lane & 3)*2;
        __half2 h0 = __floats2half2_rn(Wq[(long)n*512 + k],     Wq[(long)n*512 + k + 1]);
        __half2 h1 = __floats2half2_rn(Wq[(long)n*512 + k + 8], Wq[(long)n*512 + k + 9]);
        uint2 r; r.x = *(uint32_t*)&h0; r.y = *(uint32_t*)&h1;
        Wqf[(long)f*32 + lane] = r;
    } else {                 // Wkf fp16 (B[n][k] = Wk[k][n])
        int k16 = f & 15, n8 = f >> 4;
        int n = n8*8 + (lane >> 2);
        int k = k16*16 + (lane & 3)*2;
        __half2 h0 = __floats2half2_rn(Wk[(long)k*512 + n],     Wk[(long)(k+1)*512 + n]);
        __half2 h1 = __floats2half2_rn(Wk[(long)(k+8)*512 + n], Wk[(long)(k+9)*512 + n]);
        uint2 r; r.x = *(uint32_t*)&h0; r.y = *(uint32_t*)&h1;
        Wkf[(long)f*32 + lane] = r;
    }
}

// ===========================================================================
// proj_frag: Qkh[b][:, n0:n0+128] = ((T[b]@Wq^T) @ Wk)[:, n0:n0+128], fp16.
// grid (4 n-tiles, 16 batches), 256 thr. Fragment-direct weights, no
// inner-loop barriers. Phase A computes full Q per block (redundant x4, cheap).
// ===========================================================================
#define PF_T 0          // T: 32 x 1040
#define PF_Q 33280      // Q: 32 x 528
#define PF_BYTES 50176
#define QS_PITCH 528

__global__ __launch_bounds__(256)
void proj_frag(const float* __restrict__ T, const uint2* __restrict__ Wqf,
               const uint2* __restrict__ Wkf, __half* __restrict__ Qkh)
{
    extern __shared__ __align__(16) unsigned char sm[];
    const int nb = blockIdx.x;        // 0..3
    const int b  = blockIdx.y;        // 0..15
    const int tid  = threadIdx.x;
    const int lane = tid & 31;
    const int warp = tid >> 5;
    const int mw = warp >> 2;
    const int nw = warp & 3;
    const uint32_t smb = cvta_s(sm);

    // ---- stage T[32,512] -> fp16 smem ----
    const float* Tb = T + (long)b*KTOK*DIM;
    #pragma unroll
    for (int p = 0; p < 16; ++p) {
        int lin = tid + p*256;
        int r = lin >> 7, c4 = lin & 127;
        float4 v = *(const float4*)(Tb + (long)r*DIM + 4*c4);
        *(uint2*)(sm + PF_T + r*1040 + 8*c4) = cvt_h4(v);
    }
    __syncthreads();

    // ---- phase A: Q[32,256] = T @ Wq^T ----
    const uint32_t aT = smb + PF_T + (mw*16 + (lane & 15))*1040 + (lane >> 4)*16;
    float accQ[8][4];
    #pragma unroll
    for (int j = 0; j < 8; ++j)
        #pragma unroll
        for (int r = 0; r < 4; ++r) accQ[j][r] = 0.f;

    #pragma unroll 4
    for (int k16 = 0; k16 < 32; ++k16) {
        uint32_t a[4];
        LDSM4(a[0],a[1],a[2],a[3], aT + k16*32);
        #pragma unroll
        for (int j = 0; j < 8; ++j) {
            int n8 = nw*8 + j;
            uint2 bb = Wqf[((long)(n8*32 + k16))*32 + lane];
            MMA_F16(accQ[j], a, bb.x, bb.y);
        }
    }

    // ---- write Q -> fp16 smem ----
    const int mrow = mw*16 + (lane >> 2);
    #pragma unroll
    for (int j = 0; j < 8; ++j) {
        int col = nw*64 + j*8 + 2*(lane & 3);
        __half2 h01 = __floats2half2_rn(accQ[j][0], accQ[j][1]);
        __half2 h23 = __floats2half2_rn(accQ[j][2], accQ[j][3]);
        *(uint32_t*)(sm + PF_Q + mrow*QS_PITCH + col*2)     = *(uint32_t*)&h01;
        *(uint32_t*)(sm + PF_Q + (mrow+8)*QS_PITCH + col*2) = *(uint32_t*)&h23;
    }
    __syncthreads();

    // ---- phase B: Qk[:, n0:n0+128] = Q @ Wk ----
    const uint32_t aQ = smb + PF_Q + (mw*16 + (lane & 15))*QS_PITCH + (lane >> 4)*16;
    const int n0 = nb*128;
    float accK[4][4];
    #pragma unroll
    for (int j = 0; j < 4; ++j)
        #pragma unroll
        for (int r = 0; r < 4; ++r) accK[j][r] = 0.f;

    #pragma unroll 4
    for (int k16 = 0; k16 < 16; ++k16) {
        uint32_t a[4];
        LDSM4(a[0],a[1],a[2],a[3], aQ + k16*32);
        #pragma unroll
        for (int j = 0; j < 4; ++j) {
            int n8 = (n0 >> 3) + nw*4 + j;
            uint2 bb = Wkf[((long)(n8*16 + k16))*32 + lane];
            MMA_F16(accK[j], a, bb.x, bb.y);
        }
    }

    __half* out = Qkh + (long)b*KTOK*DIM;
    #pragma unroll
    for (int j = 0; j < 4; ++j) {
        int n = n0 + nw*32 + j*8 + 2*(lane & 3);
        __half2 h01 = __floats2half2_rn(accK[j][0], accK[j][1]);
        __half2 h23 = __floats2half2_rn(accK[j][2], accK[j][3]);
        *(uint32_t*)(out + (long)mrow*DIM + n)     = *(uint32_t*)&h01;
        *(uint32_t*)(out + (long)(mrow+8)*DIM + n) = *(uint32_t*)&h23;
    }
}

// ===========================================================================
// FUSED attention kernel v4 (verified, unchanged).
// ===========================================================================
#define QK_OFF   0
#define QK_PITCH 1040
#define E_OFF    33280
#define E_PITCH  1040
#define ES_OFF   99840
#define ES_PITCH 144
#define RED_OFF  104448
#define LP_OFF   104960
#define SMEM_FUSED 105984

__global__ __launch_bounds__(256, 2)
void fused_attn4(const __half* __restrict__ Qkh, const float* __restrict__ E,
                 const float* __restrict__ P, float* __restrict__ outA,
                 float* __restrict__ Gp, float* __restrict__ rows)
{
    extern __shared__ __align__(16) unsigned char sm[];
    const int sp = blockIdx.x;
    const int b  = blockIdx.y;
    const int tid  = threadIdx.x;
    const int lane = tid & 31;
    const int warp = tid >> 5;
    const int mw = warp >> 2;
    const int nw = warp & 3;

    const float*  Eb  = E   + (long)b*NPATCH*DIM;
    const __half* Qkb = Qkh + (long)b*KTOK*DIM;
    const float*  Pb  = P   + (long)b*NPATCH;
    float*        Ab  = outA + (long)b*KTOK*NPATCH;

    const int nbase = sp * (NPATCH/SPLITS);

    #pragma unroll
    for (int p = 0; p < 8; ++p) {
        int lin = tid + p*256;
        int r = lin >> 6, seg = lin & 63;
        uint4 v = *(const uint4*)(Qkb + r*DIM + seg*8);
        *(uint4*)(sm + QK_OFF + r*QK_PITCH + seg*16) = v;
    }
    {
        float pv = Pb[nbase + tid];
        ((float*)(sm + LP_OFF))[tid] = __logf(fminf(fmaxf(pv, 0.1f), 0.9f));
    }

    float accG[16][4];
    #pragma unroll
    for (int t2 = 0; t2 < 16; ++t2)
        #pragma unroll
        for (int r = 0; r < 4; ++r) accG[t2][r] = 0.f;
    float rsum0 = 0.f, rsum8 = 0.f;

    const uint32_t smb = cvta_s(sm);
    const uint32_t aQkBase = smb + QK_OFF + (mw*16 + (lane & 15))*QK_PITCH + (lane >> 4)*16;
    const uint32_t b1Base  = smb + E_OFF
        + (nw*16 + (lane & 7) + ((lane >> 4) & 1)*8)*E_PITCH + ((lane >> 3) & 1)*16;
    const uint32_t aEsBase = smb + ES_OFF + (mw*16 + (lane & 15))*ES_PITCH + (lane >> 4)*16;
    const uint32_t b2Base  = smb + E_OFF + (lane & 15)*E_PITCH + nw*256 + ((lane >> 4) & 1)*16;
    const float* LPs = (const float*)(sm + LP_OFF);

    for (int c = 0; c < 4; ++c) {
        const int n0 = nbase + c*64;
        __syncthreads();
        #pragma unroll 8
        for (int p = 0; p < 32; ++p) {
            int lin = tid + p*256;
            int r = lin >> 7, c4 = lin & 127;
            float4 v = *(const float4*)(Eb + (long)(n0 + r)*DIM + 4*c4);
            *(uint2*)(sm + E_OFF + r*E_PITCH + 8*c4) = cvt_h4(v);
        }
        __syncthreads();

        float sacc[2][4];
        #pragma unroll
        for (int j = 0; j < 2; ++j)
            #pragma unroll
            for (int r = 0; r < 4; ++r) sacc[j][r] = 0.f;
        #pragma unroll
        for (int ks = 0; ks < 32; ++ks) {
            uint32_t a[4], r0, r1, r2, r3;
            LDSM4(a[0],a[1],a[2],a[3], aQkBase + ks*32);
            LDSM4(r0,r1,r2,r3, b1Base + ks*32);
            MMA_F16(sacc[0], a, r0, r1);
            MMA_F16(sacc[1], a, r2, r3);
        }

        {
            const int mrow = mw*16 + (lane >> 2);
            #pragma unroll
            for (int j = 0; j < 2; ++j) {
                int nl = nw*16 + j*8 + 2*(lane & 3);
                int gn = n0 + nl;
                float lp0 = LPs[c*64 + nl];
                float lp1 = LPs[c*64 + nl + 1];
                float v0 = __expf(sacc[j][0]*SCALE_V + lp0);
                float v1 = __expf(sacc[j][1]*SCALE_V + lp1);
                float v2 = __expf(sacc[j][2]*SCALE_V + lp0);
                float v3 = __expf(sacc[j][3]*SCALE_V + lp1);
                rsum0 += v0 + v1; rsum8 += v2 + v3;
                *(float2*)(Ab + (long)mrow*NPATCH + gn)     = make_float2(v0, v1);
                *(float2*)(Ab + (long)(mrow+8)*NPATCH + gn) = make_float2(v2, v3);
                __half2 h01 = __floats2half2_rn(v0, v1);
                __half2 h23 = __floats2half2_rn(v2, v3);
                *(uint32_t*)(sm + ES_OFF + mrow*ES_PITCH + nl*2)     = *(uint32_t*)&h01;
                *(uint32_t*)(sm + ES_OFF + (mrow+8)*ES_PITCH + nl*2) = *(uint32_t*)&h23;
            }
        }
        __syncthreads();

        #pragma unroll
        for (int ks = 0; ks < 4; ++ks) {
            uint32_t a[4];
            LDSM4(a[0],a[1],a[2],a[3], aEsBase + ks*32);
            #pragma unroll
            for (int jt = 0; jt < 8; ++jt) {
                uint32_t r0, r1, r2, r3;
                LDSM4T(r0,r1,r2,r3, b2Base + ks*16*E_PITCH + jt*32);
                MMA_F16(accG[2*jt],   a, r0, r1);
                MMA_F16(accG[2*jt+1], a, r2, r3);
            }
        }
    }

    {
        float* Gpb = Gp + ((long)(b*SPLITS + sp)*KTOK)*DIM;
        const int mrow = mw*16 + (lane >> 2);
        #pragma unroll
        for (int t2 = 0; t2 < 16; ++t2) {
            int d = nw*128 + t2*8 + 2*(lane & 3);
            *(float2*)(Gpb + (long)mrow*DIM + d)     = make_float2(accG[t2][0], accG[t2][1]);
            *(float2*)(Gpb + (long)(mrow+8)*DIM + d) = make_float2(accG[t2][2], accG[t2][3]);
        }
    }

    rsum0 += __shfl_xor_sync(0xffffffffu, rsum0, 1);
    rsum0 += __shfl_xor_sync(0xffffffffu, rsum0, 2);
    rsum8 += __shfl_xor_sync(0xffffffffu, rsum8, 1);
    rsum8 += __shfl_xor_sync(0xffffffffu, rsum8, 2);
    {
        float (*srow)[4] = (float(*)[4])(sm + RED_OFF);
        __syncthreads();
        if ((lane & 3) == 0) {
            srow[mw*16 + (lane >> 2)][nw]     = rsum0;
            srow[mw*16 + 8 + (lane >> 2)][nw] = rsum8;
        }
        __syncthreads();
        if (tid < 32) {
            float s = srow[tid][0] + srow[tid][1] + srow[tid][2] + srow[tid][3];
            rows[(b*KTOK + tid)*SPLITS + sp] = s;
        }
    }
}

// ===========================================================================
// mega_tail (verified, unchanged).
// ===========================================================================
__global__ __launch_bounds__(256, 2)
void mega_tail(const float* __restrict__ Gp, float* __restrict__ G,
               const float* __restrict__ rows, float* __restrict__ A,
               const uint4* __restrict__ Wvf, const uint4* __restrict__ Wof,
               float* __restrict__ F, float* __restrict__ outF)
{
    extern __shared__ __align__(16) unsigned char sm[];
    const int bid  = blockIdx.x;
    const int tid  = threadIdx.x;
    const int lane = tid & 31;
    const int warp = tid >> 5;
    const int mw = warp >> 2;
    const int nw = warp & 3;
    const uint32_t smb = cvta_s(sm);

    // stage 1a: G reduce
    {
        int i = bid*256 + tid;
        int bb  = i >> 12;
        int rem = i & 4095;
        const float4* p = (const float4*)Gp + ((long)bb*SPLITS)*4096 + rem;
        float4 s = make_float4(0.f, 0.f, 0.f, 0.f);
        #pragma unroll
        for (int s2 = 0; s2 < SPLITS; ++s2) {
            float4 v = p[(long)s2*4096];
            s.x += v.x; s.y += v.y; s.z += v.z; s.w += v.w;
        }
        ((float4*)G)[i] = s;
    }
    // stage 1b: A rescale
    {
        float* sinv = (float*)sm;
        if (tid < 2) {
            int r = bid*2 + tid;
            float s = 0.f;
            #pragma unroll
            for (int c = 0; c < SPLITS; ++c) s += rows[r*SPLITS + c];
            sinv[tid] = 1.f / s;
        }
        __syncthreads();
        float4* pa = (float4*)(A + (long)(bid*2)*NPATCH);
        #pragma unroll
        for (int q = 0; q < 8; ++q) {
            int idx = tid + q*256;
            float s = sinv[idx >> 10];
            float4 v = pa[idx];
            v.x *= s; v.y *= s; v.z *= s; v.w *= s;
            pa[idx] = v;
        }
    }

    grid_barrier();

    // stage 2: F = G @ Wv^T (blocks < 64)
    if (bid < 64) {
        constexpr int KIN = 512, NCOLS = 256, PA = KIN*2 + 16, K16 = KIN/16, F4R = KIN/4;
        const int n0 = (bid & 3) * 64;
        const int b  = bid >> 2;
        const float* Ab = G + (long)b*KTOK*KIN;

        #pragma unroll
        for (int p = 0; p < 32*F4R/256; ++p) {
            int lin = tid + p*256;
            int r  = lin / F4R;
            int c4 = lin % F4R;
            float4 v = *(const float4*)(Ab + r*KIN + 4*c4);
            uint2 hi, lo; cvt_split4h(v, hi, lo);
            *(uint2*)(sm + r*PA + 8*c4)         = hi;
            *(uint2*)(sm + 32*PA + r*PA + 8*c4) = lo;
        }
        __syncthreads();

        const uint32_t aH = smb + (mw*16 + (lane & 15))*PA + (lane >> 4)*16;
        const uint32_t aL = aH + 32*PA;
        const int n8g = (n0 >> 3) + nw*2;
        const uint4* Wf0 = Wvf + ((long)n8g*K16)*32 + lane;
        const uint4* Wf1 = Wvf + ((long)(n8g+1)*K16)*32 + lane;

        float acc[2][4];
        #pragma unroll
        for (int j = 0; j < 2; ++j)
            #pragma unroll
            for (int r = 0; r < 4; ++r) acc[j][r] = 0.f;

        #pragma unroll 8
        for (int k16 = 0; k16 < K16; ++k16) {
            uint4 b0 = Wf0[k16*32];
            uint4 b1 = Wf1[k16*32];
            uint32_t ah[4], al[4];
            LDSM4(ah[0],ah[1],ah[2],ah[3], aH + k16*32);
            LDSM4(al[0],al[1],al[2],al[3], aL + k16*32);
            MMA_F16(acc[0], ah, b0.x, b0.y);
            MMA_F16(acc[0], ah, b0.z, b0.w);
            MMA_F16(acc[0], al, b0.x, b0.y);
            MMA_F16(acc[1], ah, b1.x, b1.y);
            MMA_F16(acc[1], ah, b1.z, b1.w);
            MMA_F16(acc[1], al, b1.x, b1.y);
        }

        const int mrow = mw*16 + (lane >> 2);
        #pragma unroll
        for (int j = 0; j < 2; ++j) {
            int n = n0 + nw*16 + j*8 + 2*(lane & 3);
            *(float2*)(F + ((long)b*KTOK + mrow)*NCOLS + n)
                = make_float2(acc[j][0], acc[j][1]);
            *(float2*)(F + ((long)b*KTOK + mrow + 8)*NCOLS + n)
                = make_float2(acc[j][2], acc[j][3]);
        }
    }

    grid_barrier();

    // stage 3: outF = F @ Wo^T (blocks < 128)
    if (bid < 128) {
        constexpr int KIN = 256, NCOLS = 512, PA = KIN*2 + 16, K16 = KIN/16, F4R = KIN/4;
        const int n0 = (bid & 7) * 64;
        const int b  = bid >> 3;
        const float* Ab = F + (long)b*KTOK*KIN;

        #pragma unroll
        for (int p = 0; p < 32*F4R/256; ++p) {
            int lin = tid + p*256;
            int r  = lin / F4R;
            int c4 = lin % F4R;
            float4 v = *(const float4*)(Ab + r*KIN + 4*c4);
            uint2 hi, lo; cvt_split4h(v, hi, lo);
            *(uint2*)(sm + r*PA + 8*c4)         = hi;
            *(uint2*)(sm + 32*PA + r*PA + 8*c4) = lo;
        }
        __syncthreads();

        const uint32_t aH = smb + (mw*16 + (lane & 15))*PA + (lane >> 4)*16;
        const uint32_t aL = aH + 32*PA;
        const int n8g = (n0 >> 3) + nw*2;
        const uint4* Wf0 = Wof + ((long)n8g*K16)*32 + lane;
        const uint4* Wf1 = Wof + ((long)(n8g+1)*K16)*32 + lane;

        float acc[2][4];
        #pragma unroll
        for (int j = 0; j < 2; ++j)
            #pragma unroll
            for (int r = 0; r < 4; ++r) acc[j][r] = 0.f;

        #pragma unroll 8
        for (int k16 = 0; k16 < K16; ++k16) {
            uint4 b0 = Wf0[k16*32];
            uint4 b1 = Wf1[k16*32];
            uint32_t ah[4], al[4];
            LDSM4(ah[0],ah[1],ah[2],ah[3], aH + k16*32);
            LDSM4(al[0],al[1],al[2],al[3], aL + k16*32);
            MMA_F16(acc[0], ah, b0.x, b0.y);
            MMA_F16(acc[0], ah, b0.z, b0.w);
            MMA_F16(acc[0], al, b0.x, b0.y);
            MMA_F16(acc[1], ah, b1.x, b1.y);
            MMA_F16(acc[1], ah, b1.z, b1.w);
            MMA_F16(acc[1], al, b1.x, b1.y);
        }

        const int mrow = mw*16 + (lane >> 2);
        #pragma unroll
        for (int j = 0; j < 2; ++j) {
            int n = n0 + nw*16 + j*8 + 2*(lane & 3);
            *(float2*)(outF + ((long)b*KTOK + mrow)*NCOLS + n)
                = make_float2(acc[j][0], acc[j][1]);
            *(float2*)(outF + ((long)b*KTOK + mrow + 8)*NCOLS + n)
                = make_float2(acc[j][2], acc[j][3]);
        }
    }

    grid_barrier();

    // stage 4: L2-normalize
    {
        float* red = (float*)sm;
        const int half = tid >> 7;
        const int t    = tid & 127;
        const int row  = bid*2 + half;
        float* p = outF + (long)row * DIM;
        float v[4]; float ss = 0.f;
        #pragma unroll
        for (int i = 0; i < 4; i++) { v[i] = p[t + i*128]; ss += v[i]*v[i]; }
        red[tid] = ss;
        __syncthreads();
        #pragma unroll
        for (int s = 64; s > 0; s >>= 1) {
            if (t < s) red[half*128 + t] += red[half*128 + t + s];
            __syncthreads();
        }
        float inv = 1.f / (sqrtf(red[half*128]) + 1e-8f);
        #pragma unroll
        for (int i = 0; i < 4; i++) p[t + i*128] = v[i] * inv;
    }
}

extern "C" void kernel_launch(void* const* d_in, const int* in_sizes, int n_in,
                              void* d_out, int out_size)
{
    const float* E  = (const float*)d_in[0];
    const float* T  = (const float*)d_in[1];
    const float* P  = (const float*)d_in[2];
    const float* Wq = (const float*)d_in[3];
    const float* Wk = (const float*)d_in[4];
    const float* Wv = (const float*)d_in[5];
    const float* Wo = (const float*)d_in[6];

    float* outF = (float*)d_out;
    float* outA = (float*)d_out + (long)BATCH*KTOK*DIM;

    float *pGp, *pG, *pF, *pRows;
    __half* pQkh;
    uint4 *pWvf, *pWof;
    uint2 *pWqf, *pWkf;
    cudaGetSymbolAddress((void**)&pQkh,  g_Qkh);
    cudaGetSymbolAddress((void**)&pGp,   g_Gp);
    cudaGetSymbolAddress((void**)&pG,    g_G);
    cudaGetSymbolAddress((void**)&pF,    g_F);
    cudaGetSymbolAddress((void**)&pRows, g_rows);
    cudaGetSymbolAddress((void**)&pWvf,  g_Wvf);
    cudaGetSymbolAddress((void**)&pWof,  g_Wof);
    cudaGetSymbolAddress((void**)&pWqf,  g_Wqf);
    cudaGetSymbolAddress((void**)&pWkf,  g_Wkf);

    const int MT_SMEM = 64*(512*2+16);   // 66560

    cudaFuncSetAttribute(fused_attn4,
        cudaFuncAttributeMaxDynamicSharedMemorySize, SMEM_FUSED);
    cudaFuncSetAttribute(mega_tail,
        cudaFuncAttributeMaxDynamicSharedMemorySize, MT_SMEM);
    cudaFuncSetAttribute(proj_frag,
        cudaFuncAttributeMaxDynamicSharedMemorySize, PF_BYTES);

    dim3 blk(256);

    // 1) all weight fragments
    prep_wfrag2<<<512, blk>>>(Wq, Wk, Wv, Wo, pWqf, pWkf, pWvf, pWof);

    // 2) Qk projection (fragment-direct)
    proj_frag<<<dim3(4, BATCH), blk, PF_BYTES>>>(T, pWqf, pWkf, pQkh);

    // 3) FUSED: expS/A(unnorm) + row-sum partials + G partials
    fused_attn4<<<dim3(SPLITS, BATCH), blk, SMEM_FUSED>>>(
        pQkh, E, P, outA, pGp, pRows);

    // 4) mega tail
    mega_tail<<<NBLK_MT, blk, MT_SMEM>>>(
        pGp, pG, pRows, outA, pWvf, pWof, pF, outF);
}

// round 16
// speedup vs baseline: 1.0399x; 1.0399x over previous
#include <cuda_runtime.h>
#include <cuda_bf16.h>
#include <cuda_fp16.h>
#include <math.h>
#include <stdint.h>

// Problem constants
#define BATCH 16
#define NPATCH 4096
#define KTOK 32
#define DIM 512
#define DHEAD 256
#define SCALE_V 0.0625f   // 256^-0.5

#define SPLITS 16         // fused grid = 16 x 16 = 256 blocks, occ 2
#define NBLK_MT 256       // mega_tail blocks (must all be co-resident)

// Scratch (no allocation allowed -> device globals)
__device__ __half g_Qkh [BATCH*KTOK*DIM];
__device__ float  g_Gp  [SPLITS*BATCH*KTOK*DIM];
__device__ float  g_G   [BATCH*KTOK*DIM];
__device__ float  g_F   [BATCH*KTOK*DHEAD];
__device__ float  g_rows[BATCH*KTOK*SPLITS];
__device__ uint4  g_Wvf [32*32*32];   // Wv fragments (hi/lo)
__device__ uint4  g_Wof [64*16*32];   // Wo fragments (hi/lo)
__device__ uint2  g_Wqf [32*32*32];   // Wq fragments (fp16)
__device__ uint2  g_Wkf [64*16*32];   // Wk^T fragments (fp16)
__device__ unsigned g_barcnt;
__device__ unsigned g_bargen;

// ---------------------------------------------------------------------------

#define LDSM4(R0,R1,R2,R3,ADDR) \
    asm volatile("ldmatrix.sync.aligned.m8n8.x4.shared.b16 {%0,%1,%2,%3}, [%4];" \
        : "=r"(R0),"=r"(R1),"=r"(R2),"=r"(R3) : "r"(ADDR))

#define LDSM4T(R0,R1,R2,R3,ADDR) \
    asm volatile("ldmatrix.sync.aligned.m8n8.x4.trans.shared.b16 {%0,%1,%2,%3}, [%4];" \
        : "=r"(R0),"=r"(R1),"=r"(R2),"=r"(R3) : "r"(ADDR))

#define MMA_F16(C,A,B0,B1) \
    asm volatile("mma.sync.aligned.m16n8k16.row.col.f32.f16.f16.f32 " \
        "{%0,%1,%2,%3},{%4,%5,%6,%7},{%8,%9},{%0,%1,%2,%3};" \
        : "+f"((C)[0]),"+f"((C)[1]),"+f"((C)[2]),"+f"((C)[3]) \
        : "r"((A)[0]),"r"((A)[1]),"r"((A)[2]),"r"((A)[3]),"r"(B0),"r"(B1))

__device__ __forceinline__ uint32_t cvta_s(const void* p) {
    return (uint32_t)__cvta_generic_to_shared(p);
}

__device__ __forceinline__ uint2 cvt_h4(float4 v) {
    __half2 h0 = __floats2half2_rn(v.x, v.y);
    __half2 h1 = __floats2half2_rn(v.z, v.w);
    uint2 r; r.x = *(uint32_t*)&h0; r.y = *(uint32_t*)&h1; return r;
}

__device__ __forceinline__ void cvt_split4h(float4 v, uint2 &hi, uint2 &lo) {
    __half2 h0 = __floats2half2_rn(v.x, v.y);
    __half2 h1 = __floats2half2_rn(v.z, v.w);
    float rx = v.x - __half2float(h0.x);
    float ry = v.y - __half2float(h0.y);
    float rz = v.z - __half2float(h1.x);
    float rw = v.w - __half2float(h1.y);
    __half2 l0 = __floats2half2_rn(rx, ry);
    __half2 l1 = __floats2half2_rn(rz, rw);
    hi.x = *(uint32_t*)&h0; hi.y = *(uint32_t*)&h1;
    lo.x = *(uint32_t*)&l0; lo.y = *(uint32_t*)&l1;
}

// Grid-wide barrier for mega_tail (all NBLK_MT blocks co-resident: occ 2).
__device__ __forceinline__ void grid_barrier() {
    __syncthreads();
    if (threadIdx.x == 0) {
        __threadfence();
        unsigned gen = atomicAdd(&g_bargen, 0u);
        if (atomicAdd(&g_barcnt, 1u) == NBLK_MT - 1u) {
            atomicExch(&g_barcnt, 0u);
            __threadfence();
            atomicAdd(&g_bargen, 1u);
        } else {
            while (atomicAdd(&g_bargen, 0u) == gen) { __nanosleep(32); }
        }
    }
    __syncthreads();
}

// ===========================================================================
// prep_qkfrag: build Wqf + Wkf (needed by proj). 256 blocks x 256 thr
// (65536 threads: t<32768 -> Wqf, t>=32768 -> Wkf).  [GRID-SIZE BUGFIX]
// ===========================================================================
__global__ __launch_bounds__(256)
void prep_qkfrag(const float* __restrict__ Wq, const float* __restrict__ Wk,
                 uint2* __restrict__ Wqf, uint2* __restrict__ Wkf)
{
    int t = blockIdx.x*256 + threadIdx.x;
    int lane = t & 31;
    int f    = (t >> 5) & 1023;
    if (t < 32768) {         // Wqf fp16 (B[n][k] = Wq[n][k], KIN=512)
        int k16 = f & 31, n8 = f >> 5;
        int n = n8*8 + (lane >> 2);
        int k = k16*16 + (lane & 3)*2;
        __half2 h0 = __floats2half2_rn(Wq[(long)n*512 + k],     Wq[(long)n*512 + k + 1]);
        __half2 h1 = __floats2half2_rn(Wq[(long)n*512 + k + 8], Wq[(long)n*512 + k + 9]);
        uint2 r; r.x = *(uint32_t*)&h0; r.y = *(uint32_t*)&h1;
        Wqf[(long)f*32 + lane] = r;
    } else {                 // Wkf fp16 (B[n][k] = Wk[k][n])
        int k16 = f & 15, n8 = f >> 4;
        int n = n8*8 + (lane >> 2);
        int k = k16*16 + (lane & 3)*2;
        __half2 h0 = __floats2half2_rn(Wk[(long)k*512 + n],     Wk[(long)(k+1)*512 + n]);
        __half2 h1 = __floats2half2_rn(Wk[(long)(k+8)*512 + n], Wk[(long)(k+9)*512 + n]);
        uint2 r; r.x = *(uint32_t*)&h0; r.y = *(uint32_t*)&h1;
        Wkf[(long)f*32 + lane] = r;
    }
}

// ===========================================================================
// proj_plus: blocks [0,64) = proj_frag; blocks [64,320) = Wvf/Wof prep.
// ===========================================================================
#define PF_T 0          // T: 32 x 1040
#define PF_Q 33280      // Q: 32 x 528
#define PF_BYTES 50176
#define QS_PITCH 528

__global__ __launch_bounds__(256)
void proj_plus(const float* __restrict__ T, const uint2* __restrict__ Wqf,
               const uint2* __restrict__ Wkf, __half* __restrict__ Qkh,
               const float* __restrict__ Wv, const float* __restrict__ Wo,
               uint4* __restrict__ Wvf, uint4* __restrict__ Wof)
{
    extern __shared__ __align__(16) unsigned char sm[];

    if (blockIdx.x >= 64) {
        // ---- Wvf / Wof fragment prep (256 blocks -> 65536 threads) ----
        int t = (blockIdx.x - 64)*256 + threadIdx.x;
        int lane = t & 31;
        int f    = (t >> 5) & 1023;
        if (t < 32768) {     // Wvf hi/lo (KIN=512, K16=32)
            int k16 = f & 31, n8 = f >> 5;
            int n = n8*8 + (lane >> 2);
            int k = k16*16 + (lane & 3)*2;
            float w00 = Wv[(long)n*512 + k],     w01 = Wv[(long)n*512 + k + 1];
            float w10 = Wv[(long)n*512 + k + 8], w11 = Wv[(long)n*512 + k + 9];
            __half2 h0 = __floats2half2_rn(w00, w01);
            __half2 h1 = __floats2half2_rn(w10, w11);
            __half2 l0 = __floats2half2_rn(w00 - __half2float(h0.x), w01 - __half2float(h0.y));
            __half2 l1 = __floats2half2_rn(w10 - __half2float(h1.x), w11 - __half2float(h1.y));
            uint4 r;
            r.x = *(uint32_t*)&h0; r.y = *(uint32_t*)&h1;
            r.z = *(uint32_t*)&l0; r.w = *(uint32_t*)&l1;
            Wvf[(long)f*32 + lane] = r;
        } else {             // Wof hi/lo (KIN=256, K16=16)
            int k16 = f & 15, n8 = f >> 4;
            int n = n8*8 + (lane >> 2);
            int k = k16*16 + (lane & 3)*2;
            float w00 = Wo[(long)n*256 + k],     w01 = Wo[(long)n*256 + k + 1];
            float w10 = Wo[(long)n*256 + k + 8], w11 = Wo[(long)n*256 + k + 9];
            __half2 h0 = __floats2half2_rn(w00, w01);
            __half2 h1 = __floats2half2_rn(w10, w11);
            __half2 l0 = __floats2half2_rn(w00 - __half2float(h0.x), w01 - __half2float(h0.y));
            __half2 l1 = __floats2half2_rn(w10 - __half2float(h1.x), w11 - __half2float(h1.y));
            uint4 r;
            r.x = *(uint32_t*)&h0; r.y = *(uint32_t*)&h1;
            r.z = *(uint32_t*)&l0; r.w = *(uint32_t*)&l1;
            Wof[(long)f*32 + lane] = r;
        }
        return;
    }

    // ---- proj_frag body (verified round 14) ----
    const int nb = blockIdx.x & 3;
    const int b  = blockIdx.x >> 2;
    const int tid  = threadIdx.x;
    const int lane = tid & 31;
    const int warp = tid >> 5;
    const int mw = warp >> 2;
    const int nw = warp & 3;
    const uint32_t smb = cvta_s(sm);

    const float* Tb = T + (long)b*KTOK*DIM;
    #pragma unroll
    for (int p = 0; p < 16; ++p) {
        int lin = tid + p*256;
        int r = lin >> 7, c4 = lin & 127;
        float4 v = *(const float4*)(Tb + (long)r*DIM + 4*c4);
        *(uint2*)(sm + PF_T + r*1040 + 8*c4) = cvt_h4(v);
    }
    __syncthreads();

    const uint32_t aT = smb + PF_T + (mw*16 + (lane & 15))*1040 + (lane >> 4)*16;
    float accQ[8][4];
    #pragma unroll
    for (int j = 0; j < 8; ++j)
        #pragma unroll
        for (int r = 0; r < 4; ++r) accQ[j][r] = 0.f;

    #pragma unroll 4
    for (int k16 = 0; k16 < 32; ++k16) {
        uint32_t a[4];
        LDSM4(a[0],a[1],a[2],a[3], aT + k16*32);
        #pragma unroll
        for (int j = 0; j < 8; ++j) {
            int n8 = nw*8 + j;
            uint2 bb = Wqf[((long)(n8*32 + k16))*32 + lane];
            MMA_F16(accQ[j], a, bb.x, bb.y);
        }
    }

    const int mrow = mw*16 + (lane >> 2);
    #pragma unroll
    for (int j = 0; j < 8; ++j) {
        int col = nw*64 + j*8 + 2*(lane & 3);
        __half2 h01 = __floats2half2_rn(accQ[j][0], accQ[j][1]);
        __half2 h23 = __floats2half2_rn(accQ[j][2], accQ[j][3]);
        *(uint32_t*)(sm + PF_Q + mrow*QS_PITCH + col*2)     = *(uint32_t*)&h01;
        *(uint32_t*)(sm + PF_Q + (mrow+8)*QS_PITCH + col*2) = *(uint32_t*)&h23;
    }
    __syncthreads();

    const uint32_t aQ = smb + PF_Q + (mw*16 + (lane & 15))*QS_PITCH + (lane >> 4)*16;
    const int n0 = nb*128;
    float accK[4][4];
    #pragma unroll
    for (int j = 0; j < 4; ++j)
        #pragma unroll
        for (int r = 0; r < 4; ++r) accK[j][r] = 0.f;

    #pragma unroll 4
    for (int k16 = 0; k16 < 16; ++k16) {
        uint32_t a[4];
        LDSM4(a[0],a[1],a[2],a[3], aQ + k16*32);
        #pragma unroll
        for (int j = 0; j < 4; ++j) {
            int n8 = (n0 >> 3) + nw*4 + j;
            uint2 bb = Wkf[((long)(n8*16 + k16))*32 + lane];
            MMA_F16(accK[j], a, bb.x, bb.y);
        }
    }

    __half* out = Qkh + (long)b*KTOK*DIM;
    #pragma unroll
    for (int j = 0; j < 4; ++j) {
        int n = n0 + nw*32 + j*8 + 2*(lane & 3);
        __half2 h01 = __floats2half2_rn(accK[j][0], accK[j][1]);
        __half2 h23 = __floats2half2_rn(accK[j][2], accK[j][3]);
        *(uint32_t*)(out + (long)mrow*DIM + n)     = *(uint32_t*)&h01;
        *(uint32_t*)(out + (long)(mrow+8)*DIM + n) = *(uint32_t*)&h23;
    }
}

// ===========================================================================
// FUSED attention kernel v4 (verified, unchanged).
// ===========================================================================
#define QK_OFF   0
#define QK_PITCH 1040
#define E_OFF    33280
#define E_PITCH  1040
#define ES_OFF   99840
#define ES_PITCH 144
#define RED_OFF  104448
#define LP_OFF   104960
#define SMEM_FUSED 105984

__global__ __launch_bounds__(256, 2)
void fused_attn4(const __half* __restrict__ Qkh, const float* __restrict__ E,
                 const float* __restrict__ P, float* __restrict__ outA,
                 float* __restrict__ Gp, float* __restrict__ rows)
{
    extern __shared__ __align__(16) unsigned char sm[];
    const int sp = blockIdx.x;
    const int b  = blockIdx.y;
    const int tid  = threadIdx.x;
    const int lane = tid & 31;
    const int warp = tid >> 5;
    const int mw = warp >> 2;
    const int nw = warp & 3;

    const float*  Eb  = E   + (long)b*NPATCH*DIM;
    const __half* Qkb = Qkh + (long)b*KTOK*DIM;
    const float*  Pb  = P   + (long)b*NPATCH;
    float*        Ab  = outA + (long)b*KTOK*NPATCH;

    const int nbase = sp * (NPATCH/SPLITS);

    #pragma unroll
    for (int p = 0; p < 8; ++p) {
        int lin = tid + p*256;
        int r = lin >> 6, seg = lin & 63;
        uint4 v = *(const uint4*)(Qkb + r*DIM + seg*8);
        *(uint4*)(sm + QK_OFF + r*QK_PITCH + seg*16) = v;
    }
    {
        float pv = Pb[nbase + tid];
        ((float*)(sm + LP_OFF))[tid] = __logf(fminf(fmaxf(pv, 0.1f), 0.9f));
    }

    float accG[16][4];
    #pragma unroll
    for (int t2 = 0; t2 < 16; ++t2)
        #pragma unroll
        for (int r = 0; r < 4; ++r) accG[t2][r] = 0.f;
    float rsum0 = 0.f, rsum8 = 0.f;

    const uint32_t smb = cvta_s(sm);
    const uint32_t aQkBase = smb + QK_OFF + (mw*16 + (lane & 15))*QK_PITCH + (lane >> 4)*16;
    const uint32_t b1Base  = smb + E_OFF
        + (nw*16 + (lane & 7) + ((lane >> 4) & 1)*8)*E_PITCH + ((lane >> 3) & 1)*16;
    const uint32_t aEsBase = smb + ES_OFF + (mw*16 + (lane & 15))*ES_PITCH + (lane >> 4)*16;
    const uint32_t b2Base  = smb + E_OFF + (lane & 15)*E_PITCH + nw*256 + ((lane >> 4) & 1)*16;
    const float* LPs = (const float*)(sm + LP_OFF);

    for (int c = 0; c < 4; ++c) {
        const int n0 = nbase + c*64;
        __syncthreads();
        #pragma unroll 8
        for (int p = 0; p < 32; ++p) {
            int lin = tid + p*256;
            int r = lin >> 7, c4 = lin & 127;
            float4 v = *(const float4*)(Eb + (long)(n0 + r)*DIM + 4*c4);
            *(uint2*)(sm + E_OFF + r*E_PITCH + 8*c4) = cvt_h4(v);
        }
        __syncthreads();

        float sacc[2][4];
        #pragma unroll
        for (int j = 0; j < 2; ++j)
            #pragma unroll
            for (int r = 0; r < 4; ++r) sacc[j][r] = 0.f;
        #pragma unroll
        for (int ks = 0; ks < 32; ++ks) {
            uint32_t a[4], r0, r1, r2, r3;
            LDSM4(a[0],a[1],a[2],a[3], aQkBase + ks*32);
            LDSM4(r0,r1,r2,r3, b1Base + ks*32);
            MMA_F16(sacc[0], a, r0, r1);
            MMA_F16(sacc[1], a, r2, r3);
        }

        {
            const int mrow = mw*16 + (lane >> 2);
            #pragma unroll
            for (int j = 0; j < 2; ++j) {
                int nl = nw*16 + j*8 + 2*(lane & 3);
                int gn = n0 + nl;
                float lp0 = LPs[c*64 + nl];
                float lp1 = LPs[c*64 + nl + 1];
                float v0 = __expf(sacc[j][0]*SCALE_V + lp0);
                float v1 = __expf(sacc[j][1]*SCALE_V + lp1);
                float v2 = __expf(sacc[j][2]*SCALE_V + lp0);
                float v3 = __expf(sacc[j][3]*SCALE_V + lp1);
                rsum0 += v0 + v1; rsum8 += v2 + v3;
                *(float2*)(Ab + (long)mrow*NPATCH + gn)     = make_float2(v0, v1);
                *(float2*)(Ab + (long)(mrow+8)*NPATCH + gn) = make_float2(v2, v3);
                __half2 h01 = __floats2half2_rn(v0, v1);
                __half2 h23 = __floats2half2_rn(v2, v3);
                *(uint32_t*)(sm + ES_OFF + mrow*ES_PITCH + nl*2)     = *(uint32_t*)&h01;
                *(uint32_t*)(sm + ES_OFF + (mrow+8)*ES_PITCH + nl*2) = *(uint32_t*)&h23;
            }
        }
        __syncthreads();

        #pragma unroll
        for (int ks = 0; ks < 4; ++ks) {
            uint32_t a[4];
            LDSM4(a[0],a[1],a[2],a[3], aEsBase + ks*32);
            #pragma unroll
            for (int jt = 0; jt < 8; ++jt) {
                uint32_t r0, r1, r2, r3;
                LDSM4T(r0,r1,r2,r3, b2Base + ks*16*E_PITCH + jt*32);
                MMA_F16(accG[2*jt],   a, r0, r1);
                MMA_F16(accG[2*jt+1], a, r2, r3);
            }
        }
    }

    {
        float* Gpb = Gp + ((long)(b*SPLITS + sp)*KTOK)*DIM;
        const int mrow = mw*16 + (lane >> 2);
        #pragma unroll
        for (int t2 = 0; t2 < 16; ++t2) {
            int d = nw*128 + t2*8 + 2*(lane & 3);
            *(float2*)(Gpb + (long)mrow*DIM + d)     = make_float2(accG[t2][0], accG[t2][1]);
            *(float2*)(Gpb + (long)(mrow+8)*DIM + d) = make_float2(accG[t2][2], accG[t2][3]);
        }
    }

    rsum0 += __shfl_xor_sync(0xffffffffu, rsum0, 1);
    rsum0 += __shfl_xor_sync(0xffffffffu, rsum0, 2);
    rsum8 += __shfl_xor_sync(0xffffffffu, rsum8, 1);
    rsum8 += __shfl_xor_sync(0xffffffffu, rsum8, 2);
    {
        float (*srow)[4] = (float(*)[4])(sm + RED_OFF);
        __syncthreads();
        if ((lane & 3) == 0) {
            srow[mw*16 + (lane >> 2)][nw]     = rsum0;
            srow[mw*16 + 8 + (lane >> 2)][nw] = rsum8;
        }
        __syncthreads();
        if (tid < 32) {
            float s = srow[tid][0] + srow[tid][1] + srow[tid][2] + srow[tid][3];
            rows[(b*KTOK + tid)*SPLITS + sp] = s;
        }
    }
}

// ===========================================================================
// mega_tail v2: 256 blocks x 256 thr, occ 2 (all co-resident).
//   stage 1: G-reduce (all blocks)
//   barrier
//   stage 2: blocks<64 F=G@Wv^T  ||  blocks [64,192) A-rescale (4 rows each)
//   barrier
//   stage 3: blocks<128 outF=F@Wo^T
//   barrier
//   stage 4: L2-normalize (2 rows/block)
// ===========================================================================
__global__ __launch_bounds__(256, 2)
void mega_tail(const float* __restrict__ Gp, float* __restrict__ G,
               const float* __restrict__ rows, float* __restrict__ A,
               const uint4* __restrict__ Wvf, const uint4* __restrict__ Wof,
               float* __restrict__ F, float* __restrict__ outF)
{
    extern __shared__ __align__(16) unsigned char sm[];
    const int bid  = blockIdx.x;
    const int tid  = threadIdx.x;
    const int lane = tid & 31;
    const int warp = tid >> 5;
    const int mw = warp >> 2;
    const int nw = warp & 3;
    const uint32_t smb = cvta_s(sm);

    // ---------- stage 1: G reduce (1 float4 per thread) ----------
    {
        int i = bid*256 + tid;               // 65536 float4
        int bb  = i >> 12;
        int rem = i & 4095;
        const float4* p = (const float4*)Gp + ((long)bb*SPLITS)*4096 + rem;
        float4 s = make_float4(0.f, 0.f, 0.f, 0.f);
        #pragma unroll
        for (int s2 = 0; s2 < SPLITS; ++s2) {
            float4 v = p[(long)s2*4096];
            s.x += v.x; s.y += v.y; s.z += v.z; s.w += v.w;
        }
        ((float4*)G)[i] = s;
    }

    grid_barrier();

    // ---------- stage 2: F GEMM (bid<64) || A rescale (bid in [64,192)) ----
    if (bid < 64) {
        constexpr int KIN = 512, NCOLS = 256, PA = KIN*2 + 16, K16 = KIN/16, F4R = KIN/4;
        const int n0 = (bid & 3) * 64;
        const int b  = bid >> 2;
        const float* Ab = G + (long)b*KTOK*KIN;

        #pragma unroll
        for (int p = 0; p < 32*F4R/256; ++p) {
            int lin = tid + p*256;
            int r  = lin / F4R;
            int c4 = lin % F4R;
            float4 v = *(const float4*)(Ab + r*KIN + 4*c4);
            uint2 hi, lo; cvt_split4h(v, hi, lo);
            *(uint2*)(sm + r*PA + 8*c4)         = hi;
            *(uint2*)(sm + 32*PA + r*PA + 8*c4) = lo;
        }
        __syncthreads();

        const uint32_t aH = smb + (mw*16 + (lane & 15))*PA + (lane >> 4)*16;
        const uint32_t aL = aH + 32*PA;
        const int n8g = (n0 >> 3) + nw*2;
        const uint4* Wf0 = Wvf + ((long)n8g*K16)*32 + lane;
        const uint4* Wf1 = Wvf + ((long)(n8g+1)*K16)*32 + lane;

        float acc[2][4];
        #pragma unroll
        for (int j = 0; j < 2; ++j)
            #pragma unroll
            for (int r = 0; r < 4; ++r) acc[j][r] = 0.f;

        #pragma unroll 8
        for (int k16 = 0; k16 < K16; ++k16) {
            uint4 b0 = Wf0[k16*32];
            uint4 b1 = Wf1[k16*32];
            uint32_t ah[4], al[4];
            LDSM4(ah[0],ah[1],ah[2],ah[3], aH + k16*32);
            LDSM4(al[0],al[1],al[2],al[3], aL + k16*32);
            MMA_F16(acc[0], ah, b0.x, b0.y);
            MMA_F16(acc[0], ah, b0.z, b0.w);
            MMA_F16(acc[0], al, b0.x, b0.y);
            MMA_F16(acc[1], ah, b1.x, b1.y);
            MMA_F16(acc[1], ah, b1.z, b1.w);
            MMA_F16(acc[1], al, b1.x, b1.y);
        }

        const int mrow = mw*16 + (lane >> 2);
        #pragma unroll
        for (int j = 0; j < 2; ++j) {
            int n = n0 + nw*16 + j*8 + 2*(lane & 3);
            *(float2*)(F + ((long)b*KTOK + mrow)*NCOLS + n)
                = make_float2(acc[j][0], acc[j][1]);
            *(float2*)(F + ((long)b*KTOK + mrow + 8)*NCOLS + n)
                = make_float2(acc[j][2], acc[j][3]);
        }
    } else if (bid < 192) {
        // A rescale: 4 rows per block (rows 4*(bid-64) .. +3)
        float* sinv = (float*)sm;
        const int r0 = (bid - 64)*4;
        if (tid < 4) {
            int r = r0 + tid;
            float s = 0.f;
            #pragma unroll
            for (int c = 0; c < SPLITS; ++c) s += rows[r*SPLITS + c];
            sinv[tid] = 1.f / s;
        }
        __syncthreads();
        float4* pa = (float4*)(A + (long)r0*NPATCH);
        #pragma unroll
        for (int q = 0; q < 16; ++q) {
            int idx = tid + q*256;           // 4096 float4 = 4 rows
            float s = sinv[idx >> 10];
            float4 v = pa[idx];
            v.x *= s; v.y *= s; v.z *= s; v.w *= s;
            pa[idx] = v;
        }
    }

    grid_barrier();

    // ---------- stage 3: outF = F @ Wo^T (blocks < 128) ----------
    if (bid < 128) {
        constexpr int KIN = 256, NCOLS = 512, PA = KIN*2 + 16, K16 = KIN/16, F4R = KIN/4;
        const int n0 = (bid & 7) * 64;
        const int b  = bid >> 3;
        const float* Ab = F + (long)b*KTOK*KIN;

        #pragma unroll
        for (int p = 0; p < 32*F4R/256; ++p) {
            int lin = tid + p*256;
            int r  = lin / F4R;
            int c4 = lin % F4R;
            float4 v = *(const float4*)(Ab + r*KIN + 4*c4);
            uint2 hi, lo; cvt_split4h(v, hi, lo);
            *(uint2*)(sm + r*PA + 8*c4)         = hi;
            *(uint2*)(sm + 32*PA + r*PA + 8*c4) = lo;
        }
        __syncthreads();

        const uint32_t aH = smb + (mw*16 + (lane & 15))*PA + (lane >> 4)*16;
        const uint32_t aL = aH + 32*PA;
        const int n8g = (n0 >> 3) + nw*2;
        const uint4* Wf0 = Wof + ((long)n8g*K16)*32 + lane;
        const uint4* Wf1 = Wof + ((long)(n8g+1)*K16)*32 + lane;

        float acc[2][4];
        #pragma unroll
        for (int j = 0; j < 2; ++j)
            #pragma unroll
            for (int r = 0; r < 4; ++r) acc[j][r] = 0.f;

        #pragma unroll 8
        for (int k16 = 0; k16 < K16; ++k16) {
            uint4 b0 = Wf0[k16*32];
            uint4 b1 = Wf1[k16*32];
            uint32_t ah[4], al[4];
            LDSM4(ah[0],ah[1],ah[2],ah[3], aH + k16*32);
            LDSM4(al[0],al[1],al[2],al[3], aL + k16*32);
            MMA_F16(acc[0], ah, b0.x, b0.y);
            MMA_F16(acc[0], ah, b0.z, b0.w);
            MMA_F16(acc[0], al, b0.x, b0.y);
            MMA_F16(acc[1], ah, b1.x, b1.y);
            MMA_F16(acc[1], ah, b1.z, b1.w);
            MMA_F16(acc[1], al, b1.x, b1.y);
        }

        const int mrow = mw*16 + (lane >> 2);
        #pragma unroll
        for (int j = 0; j < 2; ++j) {
            int n = n0 + nw*16 + j*8 + 2*(lane & 3);
            *(float2*)(outF + ((long)b*KTOK + mrow)*NCOLS + n)
                = make_float2(acc[j][0], acc[j][1]);
            *(float2*)(outF + ((long)b*KTOK + mrow + 8)*NCOLS + n)
                = make_float2(acc[j][2], acc[j][3]);
        }
    }

    grid_barrier();

    // ---------- stage 4: L2-normalize (rows 2*bid, 2*bid+1) ----------
    {
        float* red = (float*)sm;
        const int half = tid >> 7;
        const int t    = tid & 127;
        const int row  = bid*2 + half;
        float* p = outF + (long)row * DIM;
        float v[4]; float ss = 0.f;
        #pragma unroll
        for (int i = 0; i < 4; i++) { v[i] = p[t + i*128]; ss += v[i]*v[i]; }
        red[tid] = ss;
        __syncthreads();
        #pragma unroll
        for (int s = 64; s > 0; s >>= 1) {
            if (t < s) red[half*128 + t] += red[half*128 + t + s];
            __syncthreads();
        }
        float inv = 1.f / (sqrtf(red[half*128]) + 1e-8f);
        #pragma unroll
        for (int i = 0; i < 4; i++) p[t + i*128] = v[i] * inv;
    }
}

extern "C" void kernel_launch(void* const* d_in, const int* in_sizes, int n_in,
                              void* d_out, int out_size)
{
    const float* E  = (const float*)d_in[0];
    const float* T  = (const float*)d_in[1];
    const float* P  = (const float*)d_in[2];
    const float* Wq = (const float*)d_in[3];
    const float* Wk = (const float*)d_in[4];
    const float* Wv = (const float*)d_in[5];
    const float* Wo = (const float*)d_in[6];

    float* outF = (float*)d_out;
    float* outA = (float*)d_out + (long)BATCH*KTOK*DIM;

    float *pGp, *pG, *pF, *pRows;
    __half* pQkh;
    uint4 *pWvf, *pWof;
    uint2 *pWqf, *pWkf;
    cudaGetSymbolAddress((void**)&pQkh,  g_Qkh);
    cudaGetSymbolAddress((void**)&pGp,   g_Gp);
    cudaGetSymbolAddress((void**)&pG,    g_G);
    cudaGetSymbolAddress((void**)&pF,    g_F);
    cudaGetSymbolAddress((void**)&pRows, g_rows);
    cudaGetSymbolAddress((void**)&pWvf,  g_Wvf);
    cudaGetSymbolAddress((void**)&pWof,  g_Wof);
    cudaGetSymbolAddress((void**)&pWqf,  g_Wqf);
    cudaGetSymbolAddress((void**)&pWkf,  g_Wkf);

    const int MT_SMEM = 64*(512*2+16);   // 66560

    cudaFuncSetAttribute(fused_attn4,
        cudaFuncAttributeMaxDynamicSharedMemorySize, SMEM_FUSED);
    cudaFuncSetAttribute(mega_tail,
        cudaFuncAttributeMaxDynamicSharedMemorySize, MT_SMEM);
    cudaFuncSetAttribute(proj_plus,
        cudaFuncAttributeMaxDynamicSharedMemorySize, PF_BYTES);

    dim3 blk(256);

    // 1) Wq/Wk fragments (256 blocks = 65536 threads: both groups covered)
    prep_qkfrag<<<256, blk>>>(Wq, Wk, pWqf, pWkf);

    // 2) Qk projection (blocks 0-63) + Wv/Wo fragment prep (blocks 64-319)
    proj_plus<<<320, blk, PF_BYTES>>>(T, pWqf, pWkf, pQkh, Wv, Wo, pWvf, pWof);

    // 3) FUSED: expS/A(unnorm) + row-sum partials + G partials
    fused_attn4<<<dim3(SPLITS, BATCH), blk, SMEM_FUSED>>>(
        pQkh, E, P, outA, pGp, pRows);

    // 4) mega tail: G-reduce | F-GEMM || A-rescale | outF-GEMM | normalize
    mega_tail<<<NBLK_MT, blk, MT_SMEM>>>(
        pGp, pG, pRows, outA, pWvf, pWof, pF, outF);
}